// round 6
// baseline (speedup 1.0000x reference)
#include <cuda_runtime.h>
#include <cuda_bf16.h>
#include <cstdint>

// ---------------------------------------------------------------------------
// Problem constants
// ---------------------------------------------------------------------------
#define DIM   128
#define B_FIX 256
#define N_FIX 131072
#define TN    64                  // y-rows per subtile
#define SUBT  (N_FIX / TN)        // 2048
#define GRIDX 148
#define NC    (GRIDX * 4)         // 592 packed candidates per row
#define NG    15                  // groups rescored exactly (8 elems each)
#define KK    8
#define NEGF  -3.0e38f

// ---------------------------------------------------------------------------
// Global scratch (static)
// ---------------------------------------------------------------------------
__device__ uint32_t g_cpack[(size_t)B_FIX * NC];   // key16<<16 | group14
__device__ int      g_pos[B_FIX];

// SMEM layout for gemm kernel (bytes)
#define XS_OFF   0
#define XS_SIZE  (256 * 256)                 // 256 rows x 256B (bf16 swizzled)
#define YS_OFF   XS_SIZE                     // 65536
#define YS_SIZE  (64 * 256)                  // 16384 per buffer
#define SMEM_TOTAL (YS_OFF + 2 * YS_SIZE)    // 98304

// ---------------------------------------------------------------------------
// Helpers
// ---------------------------------------------------------------------------
__device__ __forceinline__ uint32_t smem_u32(const void* p) {
    uint32_t a;
    asm("{ .reg .u64 t; cvta.to.shared.u64 t, %1; cvt.u32.u64 %0, t; }"
        : "=r"(a) : "l"(p));
    return a;
}

__device__ __forceinline__ void ldsm_x4(uint32_t* r, uint32_t addr) {
    asm volatile("ldmatrix.sync.aligned.m8n8.x4.shared.b16 {%0,%1,%2,%3}, [%4];"
                 : "=r"(r[0]), "=r"(r[1]), "=r"(r[2]), "=r"(r[3]) : "r"(addr));
}

__device__ __forceinline__ void mma_bf16(float* d, const uint32_t* a,
                                         uint32_t b0, uint32_t b1) {
    asm volatile(
        "mma.sync.aligned.m16n8k16.row.col.f32.bf16.bf16.f32 "
        "{%0,%1,%2,%3}, {%4,%5,%6,%7}, {%8,%9}, {%0,%1,%2,%3};"
        : "+f"(d[0]), "+f"(d[1]), "+f"(d[2]), "+f"(d[3])
        : "r"(a[0]), "r"(a[1]), "r"(a[2]), "r"(a[3]), "r"(b0), "r"(b1));
}

// monotone uint key from float bits (order-preserving, both signs)
__device__ __forceinline__ uint32_t fkey(float v) {
    uint32_t f = __float_as_uint(v);
    return f ^ (uint32_t)(((int32_t)f >> 31) | 0x80000000);
}

// branchless sorted-descending insert chains (IMNMX only)
__device__ __forceinline__ void chain4(uint32_t* L, uint32_t m) {
#pragma unroll
    for (int j = 0; j < 4; j++) {
        uint32_t mx = max(L[j], m);
        m = min(L[j], m);
        L[j] = mx;
    }
}
__device__ __forceinline__ void chain8(uint32_t* L, uint32_t m) {
#pragma unroll
    for (int j = 0; j < 8; j++) {
        uint32_t mx = max(L[j], m);
        m = min(L[j], m);
        L[j] = mx;
    }
}

// ---------------------------------------------------------------------------
// Kernel 1: persistent bf16 mma.sync GEMM + in-register group-max mining.
//   256 threads = 8 warps; warp w owns rows w*32..w*32+31, full N=64 subtile.
//   Block 0 additionally decodes pos_inds / zeroes the output.
// ---------------------------------------------------------------------------
__global__ __launch_bounds__(256, 1)
void gemm_topk_kernel(const float* __restrict__ X, const float* __restrict__ Y,
                      const void* __restrict__ pos_inds, float* __restrict__ outp,
                      int N, int B) {
    extern __shared__ char smem[];
    __shared__ int s_not64;
    const uint32_t sb = smem_u32(smem);
    const int t    = threadIdx.x;
    const int lane = t & 31;
    const int wm   = t >> 5;      // m-group 0..7
    const int g    = lane >> 2;   // fragment row-within-8
    const int tg   = lane & 3;    // fragment col-pair
    const int bx   = blockIdx.x;

    // --- prep (block 0): zero out, sniff pos_inds dtype ---
    if (bx == 0 && t == 0) { outp[0] = 0.0f; s_not64 = 0; }
    __syncthreads();
    if (bx == 0 && t < B / 2) {
        long long v = ((const long long*)pos_inds)[t];
        if (v < 0 || v >= (long long)N) atomicExch(&s_not64, 1);
    }

    // --- load X (256x128 fp32 -> bf16) into swizzled SMEM ---
    {
        const float4* xs = (const float4*)X;
#pragma unroll
        for (int i = 0; i < 32; i++) {
            int fi = t + i * 256;
            int row = fi >> 5, c4 = fi & 31;
            float4 v = xs[fi];
            __nv_bfloat162 p0 = __float22bfloat162_rn(make_float2(v.x, v.y));
            __nv_bfloat162 p1 = __float22bfloat162_rn(make_float2(v.z, v.w));
            uint32_t off = XS_OFF + row * 256 +
                           (((c4 >> 1) ^ (row & 7)) << 4) + ((c4 & 1) << 3);
            *reinterpret_cast<uint2*>(smem + off) =
                make_uint2(*reinterpret_cast<uint32_t*>(&p0),
                           *reinterpret_cast<uint32_t*>(&p1));
        }
    }

    // --- prefetch + store first Y subtile into buffer 0 ---
    float4 pf[8];
    {
        const float4* ys = (const float4*)(Y + (size_t)bx * TN * DIM);
#pragma unroll
        for (int i = 0; i < 8; i++) pf[i] = ys[t + i * 256];
#pragma unroll
        for (int i = 0; i < 8; i++) {
            int fi = t + i * 256;
            int row = fi >> 5, c4 = fi & 31;
            __nv_bfloat162 p0 = __float22bfloat162_rn(make_float2(pf[i].x, pf[i].y));
            __nv_bfloat162 p1 = __float22bfloat162_rn(make_float2(pf[i].z, pf[i].w));
            uint32_t off = YS_OFF + row * 256 +
                           (((c4 >> 1) ^ (row & 7)) << 4) + ((c4 & 1) << 3);
            *reinterpret_cast<uint2*>(smem + off) =
                make_uint2(*reinterpret_cast<uint32_t*>(&p0),
                           *reinterpret_cast<uint32_t*>(&p1));
        }
    }
    __syncthreads();

    if (bx == 0 && t < B) {
        g_pos[t] = s_not64 ? ((const int*)pos_inds)[t]
                           : (int)((const long long*)pos_inds)[t];
    }

    // --- per-lane candidate lists: 4 rows (mt,rh) x 2 nh, top-4 keys each ---
    uint32_t L[2][2][2][4];
#pragma unroll
    for (int mt = 0; mt < 2; mt++)
#pragma unroll
        for (int rh = 0; rh < 2; rh++)
#pragma unroll
            for (int nh = 0; nh < 2; nh++)
#pragma unroll
                for (int j = 0; j < 4; j++) L[mt][rh][nh][j] = 0;

    const int sub = lane >> 3, lr = lane & 7;
    int cb = 0;
    for (int st = bx; st < SUBT; st += GRIDX) {
        const int stn = st + GRIDX;
        const bool has_next = (stn < SUBT);

        if (has_next) {
            const float4* ys = (const float4*)(Y + (size_t)stn * TN * DIM);
#pragma unroll
            for (int i = 0; i < 8; i++) pf[i] = ys[t + i * 256];
        }

        const uint32_t ysb = sb + YS_OFF + cb * YS_SIZE;
        const uint32_t gidb = ((uint32_t)st << 3) | ((uint32_t)tg << 1);

        float acc[2][8][4];
#pragma unroll
        for (int mt = 0; mt < 2; mt++)
#pragma unroll
            for (int nt = 0; nt < 8; nt++)
#pragma unroll
                for (int e = 0; e < 4; e++) acc[mt][nt][e] = 0.0f;

#pragma unroll
        for (int kt = 0; kt < 8; kt++) {
            uint32_t a[2][4], b[4][4];
            {
                int rowa = wm * 32 + ((sub & 1) << 3) + lr;
                int ca   = 2 * kt + (sub >> 1);
#pragma unroll
                for (int mt = 0; mt < 2; mt++) {
                    int row = rowa + mt * 16;
                    uint32_t addr = sb + XS_OFF + row * 256 +
                                    ((ca ^ (row & 7)) << 4);
                    ldsm_x4(a[mt], addr);
                }
            }
            {
                int rowb = ((sub >> 1) << 3) + lr;
                int cbk  = 2 * kt + (sub & 1);
#pragma unroll
                for (int p = 0; p < 4; p++) {
                    int row = rowb + p * 16;
                    uint32_t addr = ysb + row * 256 + ((cbk ^ (row & 7)) << 4);
                    ldsm_x4(b[p], addr);
                }
            }
#pragma unroll
            for (int mt = 0; mt < 2; mt++)
#pragma unroll
                for (int nt = 0; nt < 8; nt++)
                    mma_bf16(acc[mt][nt], a[mt],
                             b[nt >> 1][(nt & 1) * 2],
                             b[nt >> 1][(nt & 1) * 2 + 1]);
        }

        // --- in-register scan: per (row, nh) group-max insert ---
#pragma unroll
        for (int mt = 0; mt < 2; mt++)
#pragma unroll
            for (int rh = 0; rh < 2; rh++)
#pragma unroll
                for (int nh = 0; nh < 2; nh++) {
                    const int n0 = nh * 4;
                    float v = fmaxf(
                        fmaxf(fmaxf(acc[mt][n0+0][rh*2], acc[mt][n0+0][rh*2+1]),
                              fmaxf(acc[mt][n0+1][rh*2], acc[mt][n0+1][rh*2+1])),
                        fmaxf(fmaxf(acc[mt][n0+2][rh*2], acc[mt][n0+2][rh*2+1]),
                              fmaxf(acc[mt][n0+3][rh*2], acc[mt][n0+3][rh*2+1])));
                    uint32_t pk = (fkey(v) & 0xFFFF0000u) | gidb | (uint32_t)nh;
                    chain4(L[mt][rh][nh], pk);
                }

        if (has_next) {
            char* yd = smem + YS_OFF + (cb ^ 1) * YS_SIZE;
#pragma unroll
            for (int i = 0; i < 8; i++) {
                int fi = t + i * 256;
                int row = fi >> 5, c4 = fi & 31;
                __nv_bfloat162 p0 = __float22bfloat162_rn(make_float2(pf[i].x, pf[i].y));
                __nv_bfloat162 p1 = __float22bfloat162_rn(make_float2(pf[i].z, pf[i].w));
                uint32_t off = (uint32_t)(row * 256) +
                               (((c4 >> 1) ^ (row & 7)) << 4) + ((c4 & 1) << 3);
                *reinterpret_cast<uint2*>(yd + off) =
                    make_uint2(*reinterpret_cast<uint32_t*>(&p0),
                               *reinterpret_cast<uint32_t*>(&p1));
            }
        }
        cb ^= 1;
        __syncthreads();
    }

    // --- merge nh lists, butterfly across tg, write per (row, CTA) top-4 ---
#pragma unroll
    for (int mt = 0; mt < 2; mt++)
#pragma unroll
        for (int rh = 0; rh < 2; rh++) {
            uint32_t* l = L[mt][rh][0];
            uint32_t* m = L[mt][rh][1];
            chain4(l, m[0]); chain4(l, m[1]); chain4(l, m[2]); chain4(l, m[3]);
#pragma unroll
            for (int xb = 1; xb <= 2; xb <<= 1) {
                uint32_t o0 = __shfl_xor_sync(0xFFFFFFFFu, l[0], xb);
                uint32_t o1 = __shfl_xor_sync(0xFFFFFFFFu, l[1], xb);
                uint32_t o2 = __shfl_xor_sync(0xFFFFFFFFu, l[2], xb);
                uint32_t o3 = __shfl_xor_sync(0xFFFFFFFFu, l[3], xb);
                chain4(l, o0); chain4(l, o1); chain4(l, o2); chain4(l, o3);
            }
            if (tg == 0) {
                int row = wm * 32 + mt * 16 + rh * 8 + g;
                size_t base = (size_t)row * NC + (size_t)bx * 4;
                *reinterpret_cast<uint4*>(&g_cpack[base]) =
                    make_uint4(l[0], l[1], l[2], l[3]);
            }
        }
}

// ---------------------------------------------------------------------------
// Kernel 2: per-row merge -> top-NG groups -> exact fp32 rescore (coalesced,
//           warp-cooperative) -> exact top-num_neg -> loss -> atomicAdd
//   256 threads per block, one block per row.
// ---------------------------------------------------------------------------
__global__ __launch_bounds__(256) void merge_loss_kernel(
    const float* __restrict__ X, const float* __restrict__ Y,
    const int* __restrict__ numneg_ptr, float* __restrict__ out,
    int N, int Btot)
{
    const int b    = blockIdx.x;
    const int t    = threadIdx.x;
    const int lane = t & 31;
    const int wid  = t >> 5;

    __shared__ uint32_t cand[512];
    __shared__ uint32_t wtop[NG];
    __shared__ float    ex[NG * 8 + 1];
    __shared__ float    stop[KK];

    int num_neg = 5;
    if (numneg_ptr) {
        int nn = *numneg_ptr;
        if (nn >= 1 && nn <= KK) num_neg = nn;
    }
    const int pos = g_pos[b];

    // per-lane xrow quarter (float4) for warp-cooperative dots
    const float4 xq = ((const float4*)(X + (size_t)b * DIM))[lane];

    // stage 1: threads 0..127 keep top-4 over strided subset (<=5 each)
    if (t < 128) {
        const uint32_t* cp = g_cpack + (size_t)b * NC;
        uint32_t M[4];
#pragma unroll
        for (int j = 0; j < 4; j++) M[j] = 0;
        for (int j = t; j < NC; j += 128) chain4(M, cp[j]);
#pragma unroll
        for (int j = 0; j < 4; j++) cand[t * 4 + j] = M[j];
    }
    __syncthreads();

    // stage 2: warp 0 selects global top-NG groups from 512 survivors
    if (t < 32) {
        uint32_t W[8];
#pragma unroll
        for (int j = 0; j < 8; j++) W[j] = 0;
#pragma unroll
        for (int k = 0; k < 16; k++) chain8(W, cand[t + (k << 5)]);
        int p = 0;
        for (int r = 0; r < NG; r++) {
            uint32_t head = (p < 8) ? W[p] : 0u;
            uint32_t w = head;
#pragma unroll
            for (int off = 16; off; off >>= 1) {
                uint32_t o = __shfl_xor_sync(0xFFFFFFFFu, w, off);
                w = (o > w) ? o : w;
            }
            if (head == w && w != 0u && p < 8) p++;
            if (t == 0) wtop[r] = w;
        }
    }
    __syncthreads();

    // rescore: warp-cooperative coalesced dots, NG*8 candidates + pos
    for (int r = wid; r <= NG * 8; r += 8) {
        int col = -1;
        if (r < NG * 8) {
            uint32_t w = wtop[r >> 3];
            if (w > 0xFFFFu) {
                int grp = (int)(w & 0x3FFFu);
                int stv = grp >> 3, tgv = (grp >> 1) & 3, nhv = grp & 1;
                int e = r & 7;
                col = stv * 64 + nhv * 32 + ((e >> 1) << 3) + tgv * 2 + (e & 1);
                if (col == pos) col = -1;
            }
        } else {
            col = pos;
        }
        float d = NEGF;
        if (col >= 0 && col < N) {
            float4 yv = ((const float4*)(Y + (size_t)col * DIM))[lane];
            float s = xq.x * yv.x;
            s = fmaf(xq.y, yv.y, s);
            s = fmaf(xq.z, yv.z, s);
            s = fmaf(xq.w, yv.w, s);
#pragma unroll
            for (int off = 16; off; off >>= 1)
                s += __shfl_xor_sync(0xFFFFFFFFu, s, off);
            d = s;
        }
        if (lane == 0) ex[r] = d;
    }
    __syncthreads();

    // exact top-num_neg of ex[0..NG*8-1] via warp 0
    if (t < 32) {
        float v[4];
        int   id[4];
#pragma unroll
        for (int j = 0; j < 4; j++) {
            int p2 = t * 4 + j;
            v[j]  = (p2 < NG * 8) ? ex[p2] : NEGF;
            id[j] = p2;
        }
#pragma unroll
        for (int a2 = 0; a2 < 4; a2++)
#pragma unroll
            for (int c = a2 + 1; c < 4; c++)
                if (v[c] > v[a2] || (v[c] == v[a2] && id[c] < id[a2])) {
                    float tv = v[a2]; v[a2] = v[c]; v[c] = tv;
                    int   ti = id[a2]; id[a2] = id[c]; id[c] = ti;
                }
        int p = 0;
        for (int r = 0; r < num_neg; r++) {
            float hv = (p < 4) ? v[p] : NEGF;
            int   hi = (p < 4) ? id[p] : 1000 + t;
            float wv = hv; int wi = hi;
#pragma unroll
            for (int off = 16; off; off >>= 1) {
                float ov = __shfl_xor_sync(0xFFFFFFFFu, wv, off);
                int   oi = __shfl_xor_sync(0xFFFFFFFFu, wi, off);
                if (ov > wv || (ov == wv && oi < wi)) { wv = ov; wi = oi; }
            }
            if (hi == wi && p < 4) p++;
            if (t == 0) stop[r] = wv;
        }
    }
    __syncthreads();

    if (t == 0) {
        float sim_p = ex[NG * 8];
        float loss[KK], m[KK], mx = NEGF;
        for (int r = 0; r < num_neg; r++) {
            float sn = stop[r];
            float l = sn - sim_p + 0.3f;
            l = (l > 0.0f) ? l : 0.0f;
            float mm = (l != 0.0f) ? sn : 0.0f;
            loss[r] = l; m[r] = mm;
            if (mm > mx) mx = mm;
        }
        float ssum = 0.0f, res = 0.0f;
        float e[KK];
        for (int r = 0; r < num_neg; r++) { e[r] = expf(m[r] - mx); ssum += e[r]; }
        for (int r = 0; r < num_neg; r++) res += loss[r] * e[r];
        res /= ssum;
        atomicAdd(out, res / ((float)Btot * (float)num_neg));
    }
}

// ---------------------------------------------------------------------------
// kernel_launch
// ---------------------------------------------------------------------------
extern "C" void kernel_launch(void* const* d_in, const int* in_sizes, int n_in,
                              void* d_out, int out_size)
{
    const float* xembs  = (const float*)d_in[0];
    const float* yembs  = (const float*)d_in[1];
    const void*  posind = d_in[3];
    const int*   numneg = (n_in >= 5) ? (const int*)d_in[4] : nullptr;

    const int B = in_sizes[0] / DIM;   // 256
    const int N = in_sizes[1] / DIM;   // 131072
    float* out = (float*)d_out;

    static int smem_set = 0;
    if (!smem_set) {
        cudaFuncSetAttribute(gemm_topk_kernel,
                             cudaFuncAttributeMaxDynamicSharedMemorySize,
                             SMEM_TOTAL);
        smem_set = 1;
    }
    gemm_topk_kernel<<<GRIDX, 256, SMEM_TOTAL>>>(xembs, yembs, posind, out, N, B);
    merge_loss_kernel<<<B, 256>>>(xembs, yembs, numneg, out, N, B);
}